// round 12
// baseline (speedup 1.0000x reference)
#include <cuda_runtime.h>
#include <cuda_bf16.h>
#include <limits.h>

// Single self-sufficient kernel: block `seg` finds first/last occurrence of
// its own segment id by scanning the L2-resident mask (broadcast across
// blocks), then copies the two rows. No global scratch, no global atomics,
// trivially graph-replay-safe.
//
// 512 threads/block: doubles the warp count so the whole grid's copy loads
// issue in a shorter window (the copy is latency/issue-bound, not BW-bound).
// Thread t < 256 copies float4 t of the FIRST row; t >= 256 copies float4
// (t-256) of the LAST row -> exactly one load+store per thread.

#define NTHR 512
#define WIN  1024            // ids per window per direction (2 per thread)
#define KPT  (WIN / NTHR)    // 2

__global__ void __launch_bounds__(NTHR) fused_gather_kernel(
        const float* __restrict__ x,
        const int*   __restrict__ mask,
        float*       __restrict__ out,
        int L, int H) {
    const int seg = blockIdx.x;
    const int tid = threadIdx.x;

    __shared__ int s_first, s_last;
    if (tid == 0) { s_first = INT_MAX; s_last = -1; }

    int first = INT_MAX, last = -1;
    int fbase = 0;           // forward window base
    int bend  = L;           // backward window end (exclusive)

    while (first == INT_MAX || last < 0) {
        // ---- batched, unconditional loads for both windows ----
        int fidx[KPT], fval[KPT], bidx[KPT], bval[KPT];
        bool doF = (first == INT_MAX) && (fbase < L);
        bool doB = (last < 0) && (bend > 0);
        int bstart = bend - WIN > 0 ? bend - WIN : 0;
        #pragma unroll
        for (int k = 0; k < KPT; k++) {
            fidx[k] = fbase + tid + k * NTHR;
            bidx[k] = bstart + tid + k * NTHR;
            fval[k] = (doF && fidx[k] < L)    ? __ldg(mask + fidx[k]) : -1;
            bval[k] = (doB && bidx[k] < bend) ? __ldg(mask + bidx[k]) : -1;
        }
        // ---- local reduce, then block reduce via shared atomics ----
        int lf = INT_MAX, lb = -1;
        #pragma unroll
        for (int k = 0; k < KPT; k++) {
            if (fval[k] == seg && fidx[k] < lf) lf = fidx[k];
            if (bval[k] == seg && bidx[k] > lb) lb = bidx[k];
        }
        if (lf != INT_MAX) atomicMin(&s_first, lf);
        if (lb >= 0)       atomicMax(&s_last, lb);
        __syncthreads();
        first = s_first;
        last  = s_last;
        fbase += WIN;
        bend  = bstart;
        if ((first == INT_MAX && fbase >= L) && (last < 0 && bend <= 0)) break;
        __syncthreads();     // protect s_first/s_last reuse next round
    }

    if (first == INT_MAX || last < 0) return;   // segment absent

    // ---- copy: one float4 load+store per thread ----
    int nvec = H / 4;                            // 256 for H=1024
    float4* __restrict__ o4 = (float4*)(out + (size_t)seg * (2 * H));

    if (tid < nvec) {
        const float4* __restrict__ f4 = (const float4*)(x + (size_t)first * H);
        float4 a = __ldg(f4 + tid);
        __stcs(o4 + tid, a);                     // first-row half
    } else if (tid - nvec < nvec) {
        int t = tid - nvec;
        const float4* __restrict__ l4 = (const float4*)(x + (size_t)last * H);
        float4 b = __ldg(l4 + t);
        __stcs(o4 + nvec + t, b);                // last-row half
    }
    // generality: if H > 4*NTHR/2, mop up remaining vectors
    for (int t = tid + NTHR; t < 2 * nvec; t += NTHR) {
        if (t < nvec) {
            const float4* f4 = (const float4*)(x + (size_t)first * H);
            __stcs(o4 + t, __ldg(f4 + t));
        } else {
            const float4* l4 = (const float4*)(x + (size_t)last * H);
            __stcs(o4 + t, __ldg(l4 + (t - nvec)));
        }
    }
}

extern "C" void kernel_launch(void* const* d_in, const int* in_sizes, int n_in,
                              void* d_out, int out_size) {
    const float* x    = (const float*)d_in[0];
    const int*   mask = (const int*)d_in[1];
    float*       out  = (float*)d_out;

    int L = in_sizes[1];          // B*S = 32768
    int H = in_sizes[0] / L;      // 1024
    int n = out_size / (2 * H);   // 512

    fused_gather_kernel<<<n, NTHR>>>(x, mask, out, L, H);
}